// round 3
// baseline (speedup 1.0000x reference)
#include <cuda_runtime.h>

// ---------------------------------------------------------------------------
// Compile-time Clebsch-Gordan coefficients (Racah formula), mirroring the
// reference numpy implementation exactly (computed in double, used as float).
// ---------------------------------------------------------------------------

__host__ __device__ constexpr double cfact(int n) {
    double r = 1.0;
    for (int i = 2; i <= n; ++i) r *= (double)i;
    return r;
}

__host__ __device__ constexpr double csqrt_(double x) {
    if (x <= 0.0) return 0.0;
    double g = x > 1.0 ? x : 1.0;
    for (int i = 0; i < 100; ++i) g = 0.5 * (g + x / g);
    return g;
}

__host__ __device__ constexpr double cg_elem(int l1, int l2, int L, int m1, int m2) {
    const int M = m1 + m2;
    if (M < -L || M > L) return 0.0;
    const double pref0 = csqrt_((2.0 * L + 1.0) * cfact(L + l1 - l2) * cfact(L - l1 + l2) *
                                cfact(l1 + l2 - L) / cfact(l1 + l2 + L + 1));
    const double pref = pref0 * csqrt_(cfact(L + M) * cfact(L - M) * cfact(l1 - m1) *
                                       cfact(l1 + m1) * cfact(l2 - m2) * cfact(l2 + m2));
    double s = 0.0;
    for (int k = 0; k <= l1 + l2 - L; ++k) {
        if (l1 - m1 - k < 0 || l2 + m2 - k < 0 || L - l2 + m1 + k < 0 || L - l1 - m2 + k < 0)
            continue;
        const double d = cfact(k) * cfact(l1 + l2 - L - k) * cfact(l1 - m1 - k) *
                         cfact(l2 + m2 - k) * cfact(L - l2 + m1 + k) * cfact(L - l1 - m2 + k);
        s += ((k & 1) ? -1.0 : 1.0) / d;
    }
    return pref * s;
}

// ---------------------------------------------------------------------------
// Fully unrolled sparse CG tensor product, generated by template recursion so
// every coefficient is an FFMA immediate and all arrays stay in registers.
//
// contrib[mu,nu] += w * C[m,n,mu] * C[p,q,nu] * X1[m,p] * X2[n,q]
// CG sparsity: for a given (m,n) only mu = m+n-(l1+l2-L) can be nonzero
// (and similarly nu for (p,q)), so we loop (p,q) outer / (m,n) inner.
// ---------------------------------------------------------------------------

template <int l1, int l2, int L, int p, int q, int mn>
__device__ __forceinline__ void mn_step(const float (&X1)[(2 * l1 + 1) * (2 * l1 + 1)],
                                        const float (&X2)[(2 * l2 + 1) * (2 * l2 + 1)],
                                        float (&a)[2 * L + 1]) {
    constexpr int d1 = 2 * l1 + 1, d2 = 2 * l2 + 1;
    if constexpr (mn < d1 * d2) {
        constexpr int m = mn / d2;
        constexpr int n = mn % d2;
        constexpr int mu = m + n - (l1 + l2 - L);
        constexpr double c = cg_elem(l1, l2, L, m - l1, n - l2);
        if constexpr (mu >= 0 && mu <= 2 * L && (c > 1e-12 || c < -1e-12)) {
            a[mu] = __fmaf_rn((float)c, X1[m * d1 + p] * X2[n * d2 + q], a[mu]);
        }
        mn_step<l1, l2, L, p, q, mn + 1>(X1, X2, a);
    }
}

template <int l1, int l2, int L, int W2, int pq>
__device__ __forceinline__ void pq_step(const float (&X1)[(2 * l1 + 1) * (2 * l1 + 1)],
                                        const float (&X2)[(2 * l2 + 1) * (2 * l2 + 1)],
                                        float (&e)[(2 * L + 1) * (2 * L + 1)]) {
    constexpr int d1 = 2 * l1 + 1, d2 = 2 * l2 + 1, DL = 2 * L + 1;
    if constexpr (pq < d1 * d2) {
        constexpr int p = pq / d2;
        constexpr int q = pq % d2;
        constexpr int nu = p + q - (l1 + l2 - L);
        constexpr double cnu = cg_elem(l1, l2, L, p - l1, q - l2);
        if constexpr (nu >= 0 && nu < DL && (cnu > 1e-12 || cnu < -1e-12)) {
            float a[DL] = {};
            mn_step<l1, l2, L, p, q, 0>(X1, X2, a);
            constexpr float s = (float)((W2 ? 2.0 : 1.0) * cnu);
#pragma unroll
            for (int mu = 0; mu < DL; ++mu)
                e[mu * DL + nu] = __fmaf_rn(s, a[mu], e[mu * DL + nu]);
        }
        pq_step<l1, l2, L, W2, pq + 1>(X1, X2, e);
    }
}

// L=0 contraction of two (2L+1)x(2L+1) kernels (with the 1/(2L+1) CG factor):
// inv_L(A,B) = (1/(2L+1)) * sum_{ij} (-1)^{i+j} A[i,j] B[2L-i,2L-j]
template <int L>
__device__ __forceinline__ float invar(const float (&A)[(2 * L + 1) * (2 * L + 1)],
                                       const float (&Bm)[(2 * L + 1) * (2 * L + 1)]) {
    constexpr int D = 2 * L + 1;
    float s = 0.f;
#pragma unroll
    for (int i = 0; i < D; ++i) {
#pragma unroll
        for (int j = 0; j < D; ++j) {
            float t = A[i * D + j] * Bm[(D - 1 - i) * D + (D - 1 - j)];
            s = ((i + j) & 1) ? (s - t) : (s + t);
        }
    }
    return s * (1.0f / (float)D);
}

// ---------------------------------------------------------------------------
// Main kernel: one thread per batch element. All per-element state in regs.
// eq2 blocks (L,sigma) are built one at a time so only <=49 extra regs live.
// __syncthreads() between blocks keeps the warps of a CTA converged in the
// large unrolled instruction stream (I$ locality).
// ---------------------------------------------------------------------------

__global__ void __launch_bounds__(128)
wigner_kernel(const float* __restrict__ gx0, const float* __restrict__ gx1,
              const float* __restrict__ gx2, const float* __restrict__ gx3,
              float* __restrict__ out, int n) {
    int b = blockIdx.x * 128 + threadIdx.x;
    const bool valid = (b < n);
    const int bb = valid ? b : 0;

    float X0[1];
    float X1[9], X2[25], X3[49];
    X0[0] = gx0[bb];
#pragma unroll
    for (int i = 0; i < 9; ++i) X1[i] = gx1[bb * 9 + i];
#pragma unroll
    for (int i = 0; i < 25; ++i) X2[i] = gx2[bb * 25 + i];
#pragma unroll
    for (int i = 0; i < 49; ++i) X3[i] = gx3[bb * 49 + i];

    float out1;
    float out2 = 0.f, out3 = 0.f;

    {  // block (L=0, sigma=+): (0,0,0) (1,1,0) (2,2,0) (3,3,0)
        float e[1] = {};
        pq_step<0, 0, 0, 0, 0>(X0, X0, e);
        pq_step<1, 1, 0, 0, 0>(X1, X1, e);
        pq_step<2, 2, 0, 0, 0>(X2, X2, e);
        pq_step<3, 3, 0, 0, 0>(X3, X3, e);
        out1 = e[0];
        out2 = __fmaf_rn(e[0], X0[0], out2);
        out3 = __fmaf_rn(e[0], e[0], out3);
    }
    __syncthreads();
    {  // block (1,+): (0,1,1)x2 (1,2,1)x2 (2,3,1)x2
        float e[9] = {};
        pq_step<0, 1, 1, 1, 0>(X0, X1, e);
        pq_step<1, 2, 1, 1, 0>(X1, X2, e);
        pq_step<2, 3, 1, 1, 0>(X2, X3, e);
        out2 += invar<1>(e, X1);
        out3 += invar<1>(e, e);
    }
    __syncthreads();
    {  // block (1,-): (1,1,1) (2,2,1) (3,3,1)
        float e[9] = {};
        pq_step<1, 1, 1, 0, 0>(X1, X1, e);
        pq_step<2, 2, 1, 0, 0>(X2, X2, e);
        pq_step<3, 3, 1, 0, 0>(X3, X3, e);
        out3 += invar<1>(e, e);
    }
    __syncthreads();
    {  // block (2,+): (0,2,2)x2 (1,1,2) (1,3,2)x2 (2,2,2) (3,3,2)
        float e[25] = {};
        pq_step<0, 2, 2, 1, 0>(X0, X2, e);
        pq_step<1, 1, 2, 0, 0>(X1, X1, e);
        pq_step<1, 3, 2, 1, 0>(X1, X3, e);
        pq_step<2, 2, 2, 0, 0>(X2, X2, e);
        pq_step<3, 3, 2, 0, 0>(X3, X3, e);
        out2 += invar<2>(e, X2);
        out3 += invar<2>(e, e);
    }
    __syncthreads();
    {  // block (2,-): (1,2,2)x2 (2,3,2)x2
        float e[25] = {};
        pq_step<1, 2, 2, 1, 0>(X1, X2, e);
        pq_step<2, 3, 2, 1, 0>(X2, X3, e);
        out3 += invar<2>(e, e);
    }
    __syncthreads();
    {  // block (3,+): (0,3,3)x2 (1,2,3)x2 (2,3,3)x2
        float e[49] = {};
        pq_step<0, 3, 3, 1, 0>(X0, X3, e);
        pq_step<1, 2, 3, 1, 0>(X1, X2, e);
        pq_step<2, 3, 3, 1, 0>(X2, X3, e);
        out2 += invar<3>(e, X3);
        out3 += invar<3>(e, e);
    }
    __syncthreads();
    {  // block (3,-): (1,3,3)x2 (2,2,3) (3,3,3)
        float e[49] = {};
        pq_step<1, 3, 3, 1, 0>(X1, X3, e);
        pq_step<2, 2, 3, 0, 0>(X2, X2, e);
        pq_step<3, 3, 3, 0, 0>(X3, X3, e);
        out3 += invar<3>(e, e);
    }

    if (valid) {
        out[b * 4 + 0] = X0[0];
        out[b * 4 + 1] = out1;
        out[b * 4 + 2] = out2;
        out[b * 4 + 3] = out3;
    }
}

// ---------------------------------------------------------------------------
// Harness entry point
// ---------------------------------------------------------------------------

extern "C" void kernel_launch(void* const* d_in, const int* in_sizes, int n_in,
                              void* d_out, int out_size) {
    const float* x0 = (const float*)d_in[0];
    const float* x1 = (const float*)d_in[1];
    const float* x2 = (const float*)d_in[2];
    const float* x3 = (const float*)d_in[3];
    float* out = (float*)d_out;

    const int n = in_sizes[0];  // B (x0 is [B,1,1])
    const int grid = (n + 127) / 128;
    wigner_kernel<<<grid, 128>>>(x0, x1, x2, x3, out, n);
}

// round 4
// speedup vs baseline: 2.3276x; 2.3276x over previous
#include <cuda_runtime.h>

// ---------------------------------------------------------------------------
// Compile-time Clebsch-Gordan coefficients (Racah formula), matching numpy ref.
// ---------------------------------------------------------------------------

__host__ __device__ constexpr double cfact(int n) {
    double r = 1.0;
    for (int i = 2; i <= n; ++i) r *= (double)i;
    return r;
}

__host__ __device__ constexpr double csqrt_(double x) {
    if (x <= 0.0) return 0.0;
    double g = x > 1.0 ? x : 1.0;
    for (int i = 0; i < 100; ++i) g = 0.5 * (g + x / g);
    return g;
}

__host__ __device__ constexpr double cg_elem(int l1, int l2, int L, int m1, int m2) {
    const int M = m1 + m2;
    if (M < -L || M > L) return 0.0;
    const double pref0 = csqrt_((2.0 * L + 1.0) * cfact(L + l1 - l2) * cfact(L - l1 + l2) *
                                cfact(l1 + l2 - L) / cfact(l1 + l2 + L + 1));
    const double pref = pref0 * csqrt_(cfact(L + M) * cfact(L - M) * cfact(l1 - m1) *
                                       cfact(l1 + m1) * cfact(l2 - m2) * cfact(l2 + m2));
    double s = 0.0;
    for (int k = 0; k <= l1 + l2 - L; ++k) {
        if (l1 - m1 - k < 0 || l2 + m2 - k < 0 || L - l2 + m1 + k < 0 || L - l1 - m2 + k < 0)
            continue;
        const double d = cfact(k) * cfact(l1 + l2 - L - k) * cfact(l1 - m1 - k) *
                         cfact(l2 + m2 - k) * cfact(L - l2 + m1 + k) * cfact(L - l1 - m2 + k);
        s += ((k & 1) ? -1.0 : 1.0) / d;
    }
    return pref * s;
}

__host__ __device__ constexpr bool cg_nz(double c) { return c > 1e-12 || c < -1e-12; }

// Is there any valid p (nonzero outer CG) for this q?  (compile-time prune)
__host__ __device__ constexpr bool any_valid_p(int l1, int l2, int L, int q) {
    for (int p = 0; p <= 2 * l1; ++p) {
        int nu = p + q - (l1 + l2 - L);
        if (nu >= 0 && nu <= 2 * L && cg_nz(cg_elem(l1, l2, L, p - l1, q - l2))) return true;
    }
    return false;
}

// ---------------------------------------------------------------------------
// Operand wrappers: register-resident matrix vs smem-resident (transposed,
// one row per matrix element, lane = thread). All indices compile-time.
// ---------------------------------------------------------------------------

constexpr int STRIDE = 129;  // odd stride: conflict-free fill AND read
constexpr int R1 = 0, R2 = 9, R3 = 34, NROWS = 83;

template <int N>
struct RegMat {
    const float (&x)[N];
    template <int I> __device__ __forceinline__ float at() const { return x[I]; }
};

struct SmemMat {  // used for X3 (7x7); p = &sm[R3*STRIDE + tid]
    const float* p;
    template <int I> __device__ __forceinline__ float at() const { return p[I * STRIDE]; }
};

template <int d, int col, class M, int i = 0>
__device__ __forceinline__ void load_col(const M& mat, float (&dst)[d]) {
    if constexpr (i < d) {
        dst[i] = mat.template at<i * d + col>();
        load_col<d, col, M, i + 1>(mat, dst);
    }
}

// ---------------------------------------------------------------------------
// CG tensor product, fully unrolled. For each valid (p,q) (output column nu)
// and (m,n) (output row mu): e[mu,nu] += W*c_mn*c_pq * A[m,p]*B[n,q].
// The combined coefficient is a compile-time float immediate -> FFMA-imm.
// ---------------------------------------------------------------------------

template <int l1, int l2, int L, int p, int q, int W2, int mn>
__device__ __forceinline__ void mn_acc(const float (&acol)[2 * l1 + 1],
                                       const float (&bcol)[2 * l2 + 1],
                                       float (&e)[(2 * L + 1) * (2 * L + 1)]) {
    constexpr int d1 = 2 * l1 + 1, d2 = 2 * l2 + 1, DL = 2 * L + 1;
    if constexpr (mn < d1 * d2) {
        constexpr int m = mn / d2, n = mn % d2;
        constexpr int mu = m + n - (l1 + l2 - L);
        if constexpr (mu >= 0 && mu < DL) {
            constexpr double c = cg_elem(l1, l2, L, m - l1, n - l2);
            if constexpr (cg_nz(c)) {
                constexpr int nu = p + q - (l1 + l2 - L);
                constexpr double cn = cg_elem(l1, l2, L, p - l1, q - l2);
                constexpr float w = (float)((W2 ? 2.0 : 1.0) * c * cn);
                e[mu * DL + nu] = __fmaf_rn(w, acol[m] * bcol[n], e[mu * DL + nu]);
            }
        }
        mn_acc<l1, l2, L, p, q, W2, mn + 1>(acol, bcol, e);
    }
}

template <int l1, int l2, int L, int W2, class MA, int q, int p = 0>
__device__ __forceinline__ void p_loop(const MA& A, const float (&bcol)[2 * l2 + 1],
                                       float (&e)[(2 * L + 1) * (2 * L + 1)]) {
    constexpr int d1 = 2 * l1 + 1, DL = 2 * L + 1;
    if constexpr (p < d1) {
        constexpr int nu = p + q - (l1 + l2 - L);
        constexpr double cn = cg_elem(l1, l2, L, p - l1, q - l2);
        if constexpr (nu >= 0 && nu < DL && cg_nz(cn)) {
            float acol[d1];
            load_col<d1, p>(A, acol);
            mn_acc<l1, l2, L, p, q, W2, 0>(acol, bcol, e);
        }
        p_loop<l1, l2, L, W2, MA, q, p + 1>(A, bcol, e);
    }
}

template <int l1, int l2, int L, int W2, class MA, class MB, int q = 0>
__device__ __forceinline__ void term(const MA& A, const MB& Bm,
                                     float (&e)[(2 * L + 1) * (2 * L + 1)]) {
    constexpr int d2 = 2 * l2 + 1;
    if constexpr (q < d2) {
        if constexpr (any_valid_p(l1, l2, L, q)) {
            float bcol[d2];
            load_col<d2, q>(Bm, bcol);
            p_loop<l1, l2, L, W2, MA, q, 0>(A, bcol, e);
        }
        term<l1, l2, L, W2, MA, MB, q + 1>(A, Bm, e);
    }
}

// L=0 contraction: inv(A,B) = (1/D) * sum_ij (-1)^{i+j} A[i,j] B[D-1-i,D-1-j]
template <int L, class MB, int ij = 0>
__device__ __forceinline__ void invar_mat(const float (&A)[(2 * L + 1) * (2 * L + 1)],
                                          const MB& Bm, float& s) {
    constexpr int D = 2 * L + 1;
    if constexpr (ij < D * D) {
        constexpr int i = ij / D, j = ij % D;
        constexpr float w = (((i + j) & 1) ? -1.0f : 1.0f) / (float)D;
        s = __fmaf_rn(w, A[ij] * Bm.template at<(D - 1 - i) * D + (D - 1 - j)>(), s);
        invar_mat<L, MB, ij + 1>(A, Bm, s);
    }
}

// ---------------------------------------------------------------------------
// Kernel: one thread per batch element. X1/X2 register-resident, X3 streamed
// column-wise from transposed smem. eq2 blocks built one at a time.
// ---------------------------------------------------------------------------

__global__ void __launch_bounds__(128)
wigner_kernel(const float* __restrict__ gx0, const float* __restrict__ gx1,
              const float* __restrict__ gx2, const float* __restrict__ gx3,
              float* __restrict__ out, int n) {
    __shared__ float sm[NROWS * STRIDE];
    const int tid = threadIdx.x;
    const int base = blockIdx.x * 128;

    // Coalesced staging of X1/X2/X3 into transposed smem.
    {
        const int lim = (n - base) * 9;  // elements available for this CTA
        for (int idx = tid; idx < 9 * 128; idx += 128) {
            float v = (idx < lim) ? gx1[base * 9 + idx] : 0.f;
            sm[(R1 + idx % 9) * STRIDE + idx / 9] = v;
        }
    }
    {
        const int lim = (n - base) * 25;
        for (int idx = tid; idx < 25 * 128; idx += 128) {
            float v = (idx < lim) ? gx2[base * 25 + idx] : 0.f;
            sm[(R2 + idx % 25) * STRIDE + idx / 25] = v;
        }
    }
    {
        const int lim = (n - base) * 49;
        for (int idx = tid; idx < 49 * 128; idx += 128) {
            float v = (idx < lim) ? gx3[base * 49 + idx] : 0.f;
            sm[(R3 + idx % 49) * STRIDE + idx / 49] = v;
        }
    }
    __syncthreads();

    const int b = base + tid;
    const bool valid = (b < n);

    float X0a[1];
    X0a[0] = valid ? gx0[b] : 0.f;  // coalesced
    float X1r[9], X2r[25];
#pragma unroll
    for (int i = 0; i < 9; ++i) X1r[i] = sm[(R1 + i) * STRIDE + tid];
#pragma unroll
    for (int i = 0; i < 25; ++i) X2r[i] = sm[(R2 + i) * STRIDE + tid];

    const RegMat<1> M0{X0a};
    const RegMat<9> M1{X1r};
    const RegMat<25> M2{X2r};
    const SmemMat S3{&sm[R3 * STRIDE + tid]};

    float out1, out2 = 0.f, out3 = 0.f;

    {  // block (L=0, sigma=+): (0,0,0) (1,1,0) (2,2,0) (3,3,0)
        float e[1] = {};
        term<0, 0, 0, 0>(M0, M0, e);
        term<1, 1, 0, 0>(M1, M1, e);
        term<2, 2, 0, 0>(M2, M2, e);
        term<3, 3, 0, 0>(S3, S3, e);
        out1 = e[0];
        out2 = __fmaf_rn(e[0], X0a[0], out2);
        out3 = __fmaf_rn(e[0], e[0], out3);
    }
    __syncthreads();
    {  // block (1,+): (0,1,1)x2 (1,2,1)x2 (2,3,1)x2
        float e[9] = {};
        term<0, 1, 1, 1>(M0, M1, e);
        term<1, 2, 1, 1>(M1, M2, e);
        term<2, 3, 1, 1>(M2, S3, e);
        invar_mat<1>(e, M1, out2);
        invar_mat<1>(e, RegMat<9>{e}, out3);
    }
    __syncthreads();
    {  // block (1,-): (1,1,1) (2,2,1) (3,3,1)
        float e[9] = {};
        term<1, 1, 1, 0>(M1, M1, e);
        term<2, 2, 1, 0>(M2, M2, e);
        term<3, 3, 1, 0>(S3, S3, e);
        invar_mat<1>(e, RegMat<9>{e}, out3);
    }
    __syncthreads();
    {  // block (2,+): (0,2,2)x2 (1,1,2) (1,3,2)x2 (2,2,2) (3,3,2)
        float e[25] = {};
        term<0, 2, 2, 1>(M0, M2, e);
        term<1, 1, 2, 0>(M1, M1, e);
        term<1, 3, 2, 1>(M1, S3, e);
        term<2, 2, 2, 0>(M2, M2, e);
        term<3, 3, 2, 0>(S3, S3, e);
        invar_mat<2>(e, M2, out2);
        invar_mat<2>(e, RegMat<25>{e}, out3);
    }
    __syncthreads();
    {  // block (2,-): (1,2,2)x2 (2,3,2)x2
        float e[25] = {};
        term<1, 2, 2, 1>(M1, M2, e);
        term<2, 3, 2, 1>(M2, S3, e);
        invar_mat<2>(e, RegMat<25>{e}, out3);
    }
    __syncthreads();
    {  // block (3,+): (0,3,3)x2 (1,2,3)x2 (2,3,3)x2
        float e[49] = {};
        term<0, 3, 3, 1>(M0, S3, e);
        term<1, 2, 3, 1>(M1, M2, e);
        term<2, 3, 3, 1>(M2, S3, e);
        invar_mat<3>(e, S3, out2);
        invar_mat<3>(e, RegMat<49>{e}, out3);
    }
    __syncthreads();
    {  // block (3,-): (1,3,3)x2 (2,2,3) (3,3,3)
        float e[49] = {};
        term<1, 3, 3, 1>(M1, S3, e);
        term<2, 2, 3, 0>(M2, M2, e);
        term<3, 3, 3, 0>(S3, S3, e);
        invar_mat<3>(e, RegMat<49>{e}, out3);
    }

    if (valid) {
        reinterpret_cast<float4*>(out)[b] = make_float4(X0a[0], out1, out2, out3);
    }
}

// ---------------------------------------------------------------------------
// Harness entry point
// ---------------------------------------------------------------------------

extern "C" void kernel_launch(void* const* d_in, const int* in_sizes, int n_in,
                              void* d_out, int out_size) {
    const float* x0 = (const float*)d_in[0];
    const float* x1 = (const float*)d_in[1];
    const float* x2 = (const float*)d_in[2];
    const float* x3 = (const float*)d_in[3];
    float* out = (float*)d_out;

    const int n = in_sizes[0];  // B
    const int grid = (n + 127) / 128;
    wigner_kernel<<<grid, 128>>>(x0, x1, x2, x3, out, n);
}

// round 5
// speedup vs baseline: 3.8738x; 1.6643x over previous
#include <cuda_runtime.h>

// ---------------------------------------------------------------------------
// Compile-time Clebsch-Gordan coefficients (Racah formula), matching numpy ref.
// ---------------------------------------------------------------------------

__host__ __device__ constexpr double cfact(int n) {
    double r = 1.0;
    for (int i = 2; i <= n; ++i) r *= (double)i;
    return r;
}

__host__ __device__ constexpr double csqrt_(double x) {
    if (x <= 0.0) return 0.0;
    double g = x > 1.0 ? x : 1.0;
    for (int i = 0; i < 100; ++i) g = 0.5 * (g + x / g);
    return g;
}

__host__ __device__ constexpr double cg_elem(int l1, int l2, int L, int m1, int m2) {
    const int M = m1 + m2;
    if (M < -L || M > L) return 0.0;
    const double pref0 = csqrt_((2.0 * L + 1.0) * cfact(L + l1 - l2) * cfact(L - l1 + l2) *
                                cfact(l1 + l2 - L) / cfact(l1 + l2 + L + 1));
    const double pref = pref0 * csqrt_(cfact(L + M) * cfact(L - M) * cfact(l1 - m1) *
                                       cfact(l1 + m1) * cfact(l2 - m2) * cfact(l2 + m2));
    double s = 0.0;
    for (int k = 0; k <= l1 + l2 - L; ++k) {
        if (l1 - m1 - k < 0 || l2 + m2 - k < 0 || L - l2 + m1 + k < 0 || L - l1 - m2 + k < 0)
            continue;
        const double d = cfact(k) * cfact(l1 + l2 - L - k) * cfact(l1 - m1 - k) *
                         cfact(l2 + m2 - k) * cfact(L - l2 + m1 + k) * cfact(L - l1 - m2 + k);
        s += ((k & 1) ? -1.0 : 1.0) / d;
    }
    return pref * s;
}

__host__ __device__ constexpr bool cg_nz(double c) { return c > 1e-12 || c < -1e-12; }

// Any valid p for this q? (cross terms, full p range)
__host__ __device__ constexpr bool any_valid_p(int l1, int l2, int L, int q) {
    for (int p = 0; p <= 2 * l1; ++p) {
        int nu = p + q - (l1 + l2 - L);
        if (nu >= 0 && nu <= 2 * L && cg_nz(cg_elem(l1, l2, L, p - l1, q - l2))) return true;
    }
    return false;
}

// Any valid p <= q for this q? (symmetric self terms)
__host__ __device__ constexpr bool any_valid_p_sym(int l, int L, int q) {
    for (int p = 0; p <= q; ++p) {
        int nu = p + q - (2 * l - L);
        if (nu >= 0 && nu <= 2 * L && cg_nz(cg_elem(l, l, L, p - l, q - l))) return true;
    }
    return false;
}

// ---------------------------------------------------------------------------
// Operand wrappers: register-resident matrix vs smem-resident (transposed,
// one row per matrix element, lane = thread). All indices compile-time.
// ---------------------------------------------------------------------------

constexpr int STRIDE = 129;  // odd stride: conflict-free fill AND read
constexpr int R1 = 0, R2 = 9, R3 = 34, NROWS = 83;

template <int N>
struct RegMat {
    const float (&x)[N];
    template <int I> __device__ __forceinline__ float at() const { return x[I]; }
};

struct SmemMat {  // X3 (7x7); p = &sm[R3*STRIDE + tid]
    const float* p;
    template <int I> __device__ __forceinline__ float at() const { return p[I * STRIDE]; }
};

template <int d, int col, class M, int i = 0>
__device__ __forceinline__ void load_col(const M& mat, float (&dst)[d]) {
    if constexpr (i < d) {
        dst[i] = mat.template at<i * d + col>();
        load_col<d, col, M, i + 1>(mat, dst);
    }
}

// ---------------------------------------------------------------------------
// CG tensor product, fully unrolled, all coefficients FFMA immediates.
// e[mu,nu] += W * c_mn * c_pq * A[m,p] * B[n,q]
// BW: base weight (1 or 2).  SYMIN: restrict inner to m<=n (diagonal outer of
// a symmetric A(x)A term), doubling m<n.
// ---------------------------------------------------------------------------

template <int l1, int l2, int L, int p, int q, int BW, bool SYMIN, int mn>
__device__ __forceinline__ void mn_acc(const float (&acol)[2 * l1 + 1],
                                       const float (&bcol)[2 * l2 + 1],
                                       float (&e)[(2 * L + 1) * (2 * L + 1)]) {
    constexpr int d1 = 2 * l1 + 1, d2 = 2 * l2 + 1, DL = 2 * L + 1;
    if constexpr (mn < d1 * d2) {
        constexpr int m = mn / d2, n = mn % d2;
        constexpr int mu = m + n - (l1 + l2 - L);
        if constexpr (mu >= 0 && mu < DL && !(SYMIN && m > n)) {
            constexpr double c = cg_elem(l1, l2, L, m - l1, n - l2);
            if constexpr (cg_nz(c)) {
                constexpr int nu = p + q - (l1 + l2 - L);
                constexpr double cn = cg_elem(l1, l2, L, p - l1, q - l2);
                constexpr double wd = (double)BW * ((SYMIN && m < n) ? 2.0 : 1.0) * c * cn;
                constexpr float w = (float)wd;
                e[mu * DL + nu] = __fmaf_rn(w, acol[m] * bcol[n], e[mu * DL + nu]);
            }
        }
        mn_acc<l1, l2, L, p, q, BW, SYMIN, mn + 1>(acol, bcol, e);
    }
}

// ----- cross (A != B, or counted with W2 doubling) -----

template <int l1, int l2, int L, int W2, class MA, int q, int p = 0>
__device__ __forceinline__ void p_loop(const MA& A, const float (&bcol)[2 * l2 + 1],
                                       float (&e)[(2 * L + 1) * (2 * L + 1)]) {
    constexpr int d1 = 2 * l1 + 1, DL = 2 * L + 1;
    if constexpr (p < d1) {
        constexpr int nu = p + q - (l1 + l2 - L);
        constexpr double cn = cg_elem(l1, l2, L, p - l1, q - l2);
        if constexpr (nu >= 0 && nu < DL && cg_nz(cn)) {
            float acol[d1];
            load_col<d1, p>(A, acol);
            mn_acc<l1, l2, L, p, q, (W2 ? 2 : 1), false, 0>(acol, bcol, e);
        }
        p_loop<l1, l2, L, W2, MA, q, p + 1>(A, bcol, e);
    }
}

template <int l1, int l2, int L, int W2, class MA, class MB, int q = 0>
__device__ __forceinline__ void term(const MA& A, const MB& Bm,
                                     float (&e)[(2 * L + 1) * (2 * L + 1)]) {
    constexpr int d2 = 2 * l2 + 1;
    if constexpr (q < d2) {
        if constexpr (any_valid_p(l1, l2, L, q)) {
            float bcol[d2];
            load_col<d2, q>(Bm, bcol);
            p_loop<l1, l2, L, W2, MA, q, 0>(A, bcol, e);
        }
        term<l1, l2, L, W2, MA, MB, q + 1>(A, Bm, e);
    }
}

// ----- symmetric self term A (x) A for l1 == l2 -----
// Orbit (m,n,p,q) <-> (n,m,q,p) contributes identically: take p<q with
// weight 2 (full inner), p==q with inner m<=n (2 for m<n, 1 for m==n).

template <int l, int L, class MA, int q, int p = 0>
__device__ __forceinline__ void p_loop_sym(const MA& A, const float (&bcol)[2 * l + 1],
                                           float (&e)[(2 * L + 1) * (2 * L + 1)]) {
    constexpr int DL = 2 * L + 1;
    if constexpr (p <= q) {
        constexpr int nu = p + q - (2 * l - L);
        constexpr double cn = cg_elem(l, l, L, p - l, q - l);
        if constexpr (nu >= 0 && nu < DL && cg_nz(cn)) {
            if constexpr (p < q) {
                float acol[2 * l + 1];
                load_col<2 * l + 1, p>(A, acol);
                mn_acc<l, l, L, p, q, 2, false, 0>(acol, bcol, e);
            } else {  // p == q: reuse bcol as both operands
                mn_acc<l, l, L, p, q, 1, true, 0>(bcol, bcol, e);
            }
        }
        p_loop_sym<l, L, MA, q, p + 1>(A, bcol, e);
    }
}

template <int l, int L, class MA, int q = 0>
__device__ __forceinline__ void term_sym(const MA& A,
                                         float (&e)[(2 * L + 1) * (2 * L + 1)]) {
    constexpr int d = 2 * l + 1;
    if constexpr (q < d) {
        if constexpr (any_valid_p_sym(l, L, q)) {
            float bcol[d];
            load_col<d, q>(A, bcol);
            p_loop_sym<l, L, MA, q, 0>(A, bcol, e);
        }
        term_sym<l, L, MA, q + 1>(A, e);
    }
}

// ----- L=0 contractions -----
// inv(A,B) = (1/D) * sum_ij (-1)^{i+j} A[i,j] B[D-1-i,D-1-j]

template <int L, class MB, int ij = 0>
__device__ __forceinline__ void invar_mat(const float (&A)[(2 * L + 1) * (2 * L + 1)],
                                          const MB& Bm, float& s) {
    constexpr int D = 2 * L + 1;
    if constexpr (ij < D * D) {
        constexpr int i = ij / D, j = ij % D;
        constexpr float w = (((i + j) & 1) ? -1.0f : 1.0f) / (float)D;
        s = __fmaf_rn(w, A[ij] * Bm.template at<(D - 1 - i) * D + (D - 1 - j)>(), s);
        invar_mat<L, MB, ij + 1>(A, Bm, s);
    }
}

// Self invariant inv(A,A): partner of ij is D*D-1-ij; lower half weight 2.
template <int L, int ij = 0>
__device__ __forceinline__ void invar_self(const float (&A)[(2 * L + 1) * (2 * L + 1)],
                                           float& s) {
    constexpr int D = 2 * L + 1, DD = D * D;
    if constexpr (ij <= (DD - 1) / 2) {
        constexpr int i = ij / D, j = ij % D;
        constexpr float base = (ij == DD - 1 - ij) ? 1.0f : 2.0f;
        constexpr float w = (((i + j) & 1) ? -base : base) / (float)D;
        s = __fmaf_rn(w, A[ij] * A[DD - 1 - ij], s);
        invar_self<L, ij + 1>(A, s);
    }
}

// ---------------------------------------------------------------------------
// Kernel: one thread per batch element. X1/X2 in registers, X3 streamed from
// transposed smem. Register cap 128 (4 CTAs/SM) for latency hiding.
// ---------------------------------------------------------------------------

__global__ void __launch_bounds__(128, 4)
wigner_kernel(const float* __restrict__ gx0, const float* __restrict__ gx1,
              const float* __restrict__ gx2, const float* __restrict__ gx3,
              float* __restrict__ out, int n) {
    __shared__ float sm[NROWS * STRIDE];
    const int tid = threadIdx.x;
    const int base = blockIdx.x * 128;

    // Coalesced staging into transposed smem.
    {
        const int lim = (n - base) * 9;
        for (int idx = tid; idx < 9 * 128; idx += 128) {
            float v = (idx < lim) ? gx1[base * 9 + idx] : 0.f;
            sm[(R1 + idx % 9) * STRIDE + idx / 9] = v;
        }
    }
    {
        const int lim = (n - base) * 25;
        for (int idx = tid; idx < 25 * 128; idx += 128) {
            float v = (idx < lim) ? gx2[base * 25 + idx] : 0.f;
            sm[(R2 + idx % 25) * STRIDE + idx / 25] = v;
        }
    }
    {
        const int lim = (n - base) * 49;
        for (int idx = tid; idx < 49 * 128; idx += 128) {
            float v = (idx < lim) ? gx3[base * 49 + idx] : 0.f;
            sm[(R3 + idx % 49) * STRIDE + idx / 49] = v;
        }
    }
    __syncthreads();

    const int b = base + tid;
    const bool valid = (b < n);

    float X0a[1];
    X0a[0] = valid ? gx0[b] : 0.f;
    float X1r[9], X2r[25];
#pragma unroll
    for (int i = 0; i < 9; ++i) X1r[i] = sm[(R1 + i) * STRIDE + tid];
#pragma unroll
    for (int i = 0; i < 25; ++i) X2r[i] = sm[(R2 + i) * STRIDE + tid];

    const RegMat<1> M0{X0a};
    const RegMat<9> M1{X1r};
    const RegMat<25> M2{X2r};
    const SmemMat S3{&sm[R3 * STRIDE + tid]};

    float out1, out2 = 0.f, out3 = 0.f;

    {  // block (L=0, +): (0,0,0) (1,1,0) (2,2,0) (3,3,0)  all self-symmetric
        float e[1] = {};
        term_sym<0, 0>(M0, e);
        term_sym<1, 0>(M1, e);
        term_sym<2, 0>(M2, e);
        term_sym<3, 0>(S3, e);
        out1 = e[0];
        out2 = __fmaf_rn(e[0], X0a[0], out2);
        out3 = __fmaf_rn(e[0], e[0], out3);
    }
    __syncthreads();
    {  // block (1,+): (0,1,1)x2 (1,2,1)x2 (2,3,1)x2
        float e[9] = {};
        term<0, 1, 1, 1>(M0, M1, e);
        term<1, 2, 1, 1>(M1, M2, e);
        term<2, 3, 1, 1>(M2, S3, e);
        invar_mat<1>(e, M1, out2);
        invar_self<1>(e, out3);
    }
    __syncthreads();
    {  // block (1,-): (1,1,1) (2,2,1) (3,3,1)  all self-symmetric
        float e[9] = {};
        term_sym<1, 1>(M1, e);
        term_sym<2, 1>(M2, e);
        term_sym<3, 1>(S3, e);
        invar_self<1>(e, out3);
    }
    __syncthreads();
    {  // block (2,+): (0,2,2)x2 (1,1,2) (1,3,2)x2 (2,2,2) (3,3,2)
        float e[25] = {};
        term<0, 2, 2, 1>(M0, M2, e);
        term_sym<1, 2>(M1, e);
        term<1, 3, 2, 1>(M1, S3, e);
        term_sym<2, 2>(M2, e);
        term_sym<3, 2>(S3, e);
        invar_mat<2>(e, M2, out2);
        invar_self<2>(e, out3);
    }
    __syncthreads();
    {  // block (2,-): (1,2,2)x2 (2,3,2)x2
        float e[25] = {};
        term<1, 2, 2, 1>(M1, M2, e);
        term<2, 3, 2, 1>(M2, S3, e);
        invar_self<2>(e, out3);
    }
    __syncthreads();
    {  // block (3,+): (0,3,3)x2 (1,2,3)x2 (2,3,3)x2
        float e[49] = {};
        term<0, 3, 3, 1>(M0, S3, e);
        term<1, 2, 3, 1>(M1, M2, e);
        term<2, 3, 3, 1>(M2, S3, e);
        invar_mat<3>(e, S3, out2);
        invar_self<3>(e, out3);
    }
    __syncthreads();
    {  // block (3,-): (1,3,3)x2 (2,2,3) (3,3,3)
        float e[49] = {};
        term<1, 3, 3, 1>(M1, S3, e);
        term_sym<2, 3>(M2, e);
        term_sym<3, 3>(S3, e);
        invar_self<3>(e, out3);
    }

    if (valid) {
        reinterpret_cast<float4*>(out)[b] = make_float4(X0a[0], out1, out2, out3);
    }
}

// ---------------------------------------------------------------------------
// Harness entry point
// ---------------------------------------------------------------------------

extern "C" void kernel_launch(void* const* d_in, const int* in_sizes, int n_in,
                              void* d_out, int out_size) {
    const float* x0 = (const float*)d_in[0];
    const float* x1 = (const float*)d_in[1];
    const float* x2 = (const float*)d_in[2];
    const float* x3 = (const float*)d_in[3];
    float* out = (float*)d_out;

    const int n = in_sizes[0];  // B
    const int grid = (n + 127) / 128;
    wigner_kernel<<<grid, 128>>>(x0, x1, x2, x3, out, n);
}

// round 6
// speedup vs baseline: 4.7183x; 1.2180x over previous
#include <cuda_runtime.h>

// ---------------------------------------------------------------------------
// Compile-time Clebsch-Gordan coefficients (Racah formula), matching numpy ref.
// ---------------------------------------------------------------------------

__host__ __device__ constexpr double cfact(int n) {
    double r = 1.0;
    for (int i = 2; i <= n; ++i) r *= (double)i;
    return r;
}

__host__ __device__ constexpr double csqrt_(double x) {
    if (x <= 0.0) return 0.0;
    double g = x > 1.0 ? x : 1.0;
    for (int i = 0; i < 100; ++i) g = 0.5 * (g + x / g);
    return g;
}

__host__ __device__ constexpr double cg_elem(int l1, int l2, int L, int m1, int m2) {
    const int M = m1 + m2;
    if (M < -L || M > L) return 0.0;
    const double pref0 = csqrt_((2.0 * L + 1.0) * cfact(L + l1 - l2) * cfact(L - l1 + l2) *
                                cfact(l1 + l2 - L) / cfact(l1 + l2 + L + 1));
    const double pref = pref0 * csqrt_(cfact(L + M) * cfact(L - M) * cfact(l1 - m1) *
                                       cfact(l1 + m1) * cfact(l2 - m2) * cfact(l2 + m2));
    double s = 0.0;
    for (int k = 0; k <= l1 + l2 - L; ++k) {
        if (l1 - m1 - k < 0 || l2 + m2 - k < 0 || L - l2 + m1 + k < 0 || L - l1 - m2 + k < 0)
            continue;
        const double d = cfact(k) * cfact(l1 + l2 - L - k) * cfact(l1 - m1 - k) *
                         cfact(l2 + m2 - k) * cfact(L - l2 + m1 + k) * cfact(L - l1 - m2 + k);
        s += ((k & 1) ? -1.0 : 1.0) / d;
    }
    return pref * s;
}

__host__ __device__ constexpr bool cg_nz(double c) { return c > 1e-12 || c < -1e-12; }

// (a,b) index pair valid at level L (index form: a in [0,2l1], b in [0,2l2])
__host__ __device__ constexpr bool okL(int l1, int l2, int L, int a, int b) {
    const int off = l1 + l2 - L;
    const int mu = a + b - off;
    return mu >= 0 && mu <= 2 * L && cg_nz(cg_elem(l1, l2, L, a - l1, b - l2));
}

__host__ __device__ constexpr bool pair_any(int l1, int l2, int Lmin, int Lmax,
                                            int p, int q, int m, int n) {
    for (int L = Lmin; L <= Lmax; ++L)
        if (okL(l1, l2, L, m, n) && okL(l1, l2, L, p, q)) return true;
    return false;
}

__host__ __device__ constexpr bool col_any_p(int l1, int l2, int Lmin, int Lmax, int p, int q) {
    for (int L = Lmin; L <= Lmax; ++L)
        if (okL(l1, l2, L, p, q)) return true;
    return false;
}

__host__ __device__ constexpr bool col_any_q(int l1, int l2, int Lmin, int Lmax, int q, bool sym) {
    const int pmax = sym ? q : 2 * l1;
    for (int p = 0; p <= pmax; ++p)
        if (col_any_p(l1, l2, Lmin, Lmax, p, q)) return true;
    return false;
}

// ---------------------------------------------------------------------------
// Smem operand wrapper (transposed layout: element-row x lane), compile-time idx.
// ---------------------------------------------------------------------------

constexpr int STRIDE = 129;  // odd stride: conflict-free fill AND read
constexpr int R1 = 0, R2 = 9, R3 = 34, NROWS = 83;

struct SmemMat {
    const float* p;
    template <int I> __device__ __forceinline__ float at() const { return p[I * STRIDE]; }
};

template <int d, int col, class M, int i = 0>
__device__ __forceinline__ void load_col(const M& mat, float (&dst)[d]) {
    if constexpr (i < d) {
        dst[i] = mat.template at<i * d + col>();
        load_col<d, col, M, i + 1>(mat, dst);
    }
}

// ---------------------------------------------------------------------------
// Accumulator group: one array per L (phase maps L -> a specific (L,sigma) block)
// ---------------------------------------------------------------------------

struct EAcc {
    float e0[1];
    float e1[9];
    float e2[25];
    float e3[49];
};

template <int L> __device__ __forceinline__ auto& getE(EAcc& a) {
    if constexpr (L == 0) return a.e0;
    else if constexpr (L == 1) return a.e1;
    else if constexpr (L == 2) return a.e2;
    else return a.e3;
}

template <int N>
__device__ __forceinline__ void zeroa(float (&e)[N]) {
#pragma unroll
    for (int i = 0; i < N; ++i) e[i] = 0.f;
}

// ---------------------------------------------------------------------------
// Shared-product CG scatter: one FMUL per (m,n,p,q), one FFMA-imm per valid L.
// ---------------------------------------------------------------------------

template <int l1, int l2, int p, int q, int m, int n, int W, int L, int Lmax>
__device__ __forceinline__ void l_scatter(float prod, EAcc& acc) {
    if constexpr (L <= Lmax) {
        if constexpr (okL(l1, l2, L, m, n) && okL(l1, l2, L, p, q)) {
            constexpr int off = l1 + l2 - L, DL = 2 * L + 1;
            constexpr int mu = m + n - off, nu = p + q - off;
            constexpr float w = (float)((double)W * cg_elem(l1, l2, L, m - l1, n - l2) *
                                        cg_elem(l1, l2, L, p - l1, q - l2));
            getE<L>(acc)[mu * DL + nu] = __fmaf_rn(w, prod, getE<L>(acc)[mu * DL + nu]);
        }
        l_scatter<l1, l2, p, q, m, n, W, L + 1, Lmax>(prod, acc);
    }
}

template <int l1, int l2, int p, int q, int BW, bool SYMIN, int Lmin, int Lmax, int mn = 0>
__device__ __forceinline__ void mn_multi(const float (&acol)[2 * l1 + 1],
                                         const float (&bcol)[2 * l2 + 1], EAcc& acc) {
    constexpr int d1 = 2 * l1 + 1, d2 = 2 * l2 + 1;
    if constexpr (mn < d1 * d2) {
        constexpr int m = mn / d2, n = mn % d2;
        if constexpr (!(SYMIN && m > n) && pair_any(l1, l2, Lmin, Lmax, p, q, m, n)) {
            float prod = acol[m] * bcol[n];
            l_scatter<l1, l2, p, q, m, n, BW*((SYMIN && m < n) ? 2 : 1), Lmin, Lmax>(prod, acc);
        }
        mn_multi<l1, l2, p, q, BW, SYMIN, Lmin, Lmax, mn + 1>(acol, bcol, acc);
    }
}

// ----- cross term (A != B), weight BW (2 for the (l1,l2)+(l2,l1) fold) -----

template <int l1, int l2, int BW, int Lmin, int Lmax, class MA, int q, int p = 0>
__device__ __forceinline__ void p_multi(const MA& A, const float (&bcol)[2 * l2 + 1],
                                        EAcc& acc) {
    constexpr int d1 = 2 * l1 + 1;
    if constexpr (p < d1) {
        if constexpr (col_any_p(l1, l2, Lmin, Lmax, p, q)) {
            float acol[d1];
            load_col<d1, p>(A, acol);
            mn_multi<l1, l2, p, q, BW, false, Lmin, Lmax>(acol, bcol, acc);
        }
        p_multi<l1, l2, BW, Lmin, Lmax, MA, q, p + 1>(A, bcol, acc);
    }
}

template <int l1, int l2, int BW, int Lmin, int Lmax, class MA, class MB, int q = 0>
__device__ __forceinline__ void term_multi(const MA& A, const MB& Bm, EAcc& acc) {
    constexpr int d2 = 2 * l2 + 1;
    if constexpr (q < d2) {
        if constexpr (col_any_q(l1, l2, Lmin, Lmax, q, false)) {
            float bcol[d2];
            load_col<d2, q>(Bm, bcol);
            p_multi<l1, l2, BW, Lmin, Lmax, MA, q>(A, bcol, acc);
        }
        term_multi<l1, l2, BW, Lmin, Lmax, MA, MB, q + 1>(A, Bm, acc);
    }
}

// ----- symmetric self term A(x)A: p<q weight 2 full inner; p==q inner m<=n -----

template <int l, int Lmin, int Lmax, class MA, int q, int p = 0>
__device__ __forceinline__ void p_sym_multi(const MA& A, const float (&bcol)[2 * l + 1],
                                            EAcc& acc) {
    if constexpr (p <= q) {
        if constexpr (col_any_p(l, l, Lmin, Lmax, p, q)) {
            if constexpr (p < q) {
                float acol[2 * l + 1];
                load_col<2 * l + 1, p>(A, acol);
                mn_multi<l, l, p, q, 2, false, Lmin, Lmax>(acol, bcol, acc);
            } else {
                mn_multi<l, l, p, q, 1, true, Lmin, Lmax>(bcol, bcol, acc);
            }
        }
        p_sym_multi<l, Lmin, Lmax, MA, q, p + 1>(A, bcol, acc);
    }
}

template <int l, int Lmin, int Lmax, class MA, int q = 0>
__device__ __forceinline__ void term_sym_multi(const MA& A, EAcc& acc) {
    constexpr int d = 2 * l + 1;
    if constexpr (q < d) {
        if constexpr (col_any_q(l, l, Lmin, Lmax, q, true)) {
            float bcol[d];
            load_col<d, q>(A, bcol);
            p_sym_multi<l, Lmin, Lmax, MA, q>(A, bcol, acc);
        }
        term_sym_multi<l, Lmin, Lmax, MA, q + 1>(A, acc);
    }
}

// ----- (0,l) degenerate term: e_l[i] += t * X_l[i]  (t = 2*X0) -----

template <int N, class M, int i = 0>
__device__ __forceinline__ void axpy_sm(float t, const M& X, float (&e)[N]) {
    if constexpr (i < N) {
        e[i] = __fmaf_rn(t, X.template at<i>(), e[i]);
        axpy_sm<N, M, i + 1>(t, X, e);
    }
}

// ----- L=0 contractions -----

template <int L, class MB, int ij = 0>
__device__ __forceinline__ void invar_mat(const float (&A)[(2 * L + 1) * (2 * L + 1)],
                                          const MB& Bm, float& s) {
    constexpr int D = 2 * L + 1;
    if constexpr (ij < D * D) {
        constexpr int i = ij / D, j = ij % D;
        constexpr float w = (((i + j) & 1) ? -1.0f : 1.0f) / (float)D;
        s = __fmaf_rn(w, A[ij] * Bm.template at<(D - 1 - i) * D + (D - 1 - j)>(), s);
        invar_mat<L, MB, ij + 1>(A, Bm, s);
    }
}

template <int L, int ij = 0>
__device__ __forceinline__ void invar_self(const float (&A)[(2 * L + 1) * (2 * L + 1)],
                                           float& s) {
    constexpr int D = 2 * L + 1, DD = D * D;
    if constexpr (ij <= (DD - 1) / 2) {
        constexpr int i = ij / D, j = ij % D;
        constexpr float base = (ij == DD - 1 - ij) ? 1.0f : 2.0f;
        constexpr float w = (((i + j) & 1) ? -base : base) / (float)D;
        s = __fmaf_rn(w, A[ij] * A[DD - 1 - ij], s);
        invar_self<L, ij + 1>(A, s);
    }
}

// ---------------------------------------------------------------------------
// Kernel: one thread per batch element, two phases of sigma-parity groups.
// Phase A (l1+l2 even): blocks (0,+),(1,-),(2,+),(3,-) as e0,e1,e2,e3.
// Phase B (l1+l2 odd):  blocks (1,+),(2,-),(3,+)     as e1,e2,e3.
// All X matrices streamed column-wise from transposed smem; each data product
// computed once and scattered into every valid L with an FFMA-immediate.
// ---------------------------------------------------------------------------

__global__ void __launch_bounds__(128, 4)
wigner_kernel(const float* __restrict__ gx0, const float* __restrict__ gx1,
              const float* __restrict__ gx2, const float* __restrict__ gx3,
              float* __restrict__ out, int n) {
    __shared__ float sm[NROWS * STRIDE];
    const int tid = threadIdx.x;
    const int base = blockIdx.x * 128;

    // Coalesced staging into transposed smem.
    {
        const int lim = (n - base) * 9;
        for (int idx = tid; idx < 9 * 128; idx += 128) {
            float v = (idx < lim) ? gx1[base * 9 + idx] : 0.f;
            sm[(R1 + idx % 9) * STRIDE + idx / 9] = v;
        }
    }
    {
        const int lim = (n - base) * 25;
        for (int idx = tid; idx < 25 * 128; idx += 128) {
            float v = (idx < lim) ? gx2[base * 25 + idx] : 0.f;
            sm[(R2 + idx % 25) * STRIDE + idx / 25] = v;
        }
    }
    {
        const int lim = (n - base) * 49;
        for (int idx = tid; idx < 49 * 128; idx += 128) {
            float v = (idx < lim) ? gx3[base * 49 + idx] : 0.f;
            sm[(R3 + idx % 49) * STRIDE + idx / 49] = v;
        }
    }
    __syncthreads();

    const int b = base + tid;
    const bool valid = (b < n);
    const float X0 = valid ? gx0[b] : 0.f;

    const SmemMat S1{&sm[R1 * STRIDE + tid]};
    const SmemMat S2{&sm[R2 * STRIDE + tid]};
    const SmemMat S3{&sm[R3 * STRIDE + tid]};

    float out1, out2 = 0.f, out3 = 0.f;
    const float twoX0 = X0 + X0;

    {  // ---------------- Phase A: terms with l1+l2 even ----------------
        EAcc A_;
        zeroa(A_.e0); zeroa(A_.e1); zeroa(A_.e2); zeroa(A_.e3);

        A_.e0[0] = X0 * X0;                    // (0,0) -> L=0
        term_sym_multi<1, 0, 2>(S1, A_);       // (1,1) -> L=0,1,2
        term_sym_multi<2, 0, 3>(S2, A_);       // (2,2) -> L=0..3
        term_sym_multi<3, 0, 3>(S3, A_);       // (3,3) -> L=0..3
        axpy_sm<25>(twoX0, S2, A_.e2);         // (0,2)x2 -> L=2
        term_multi<1, 3, 2, 2, 3>(S1, S3, A_); // (1,3)x2 -> L=2,3

        out1 = A_.e0[0];
        out2 = __fmaf_rn(A_.e0[0], X0, out2);
        out3 = __fmaf_rn(A_.e0[0], A_.e0[0], out3);
        invar_self<1>(A_.e1, out3);            // (1,-)
        invar_mat<2>(A_.e2, S2, out2);         // (2,+) x X2
        invar_self<2>(A_.e2, out3);
        invar_self<3>(A_.e3, out3);            // (3,-)
    }
    __syncthreads();
    {  // ---------------- Phase B: terms with l1+l2 odd ----------------
        EAcc Bb;
        zeroa(Bb.e1); zeroa(Bb.e2); zeroa(Bb.e3);

        axpy_sm<9>(twoX0, S1, Bb.e1);          // (0,1)x2 -> L=1
        term_multi<1, 2, 2, 1, 3>(S1, S2, Bb); // (1,2)x2 -> L=1..3
        term_multi<2, 3, 2, 1, 3>(S2, S3, Bb); // (2,3)x2 -> L=1..3
        axpy_sm<49>(twoX0, S3, Bb.e3);         // (0,3)x2 -> L=3

        invar_mat<1>(Bb.e1, S1, out2);         // (1,+) x X1
        invar_self<1>(Bb.e1, out3);
        invar_self<2>(Bb.e2, out3);            // (2,-)
        invar_mat<3>(Bb.e3, S3, out2);         // (3,+) x X3
        invar_self<3>(Bb.e3, out3);
    }

    if (valid) {
        reinterpret_cast<float4*>(out)[b] = make_float4(X0, out1, out2, out3);
    }
}

// ---------------------------------------------------------------------------
// Harness entry point
// ---------------------------------------------------------------------------

extern "C" void kernel_launch(void* const* d_in, const int* in_sizes, int n_in,
                              void* d_out, int out_size) {
    const float* x0 = (const float*)d_in[0];
    const float* x1 = (const float*)d_in[1];
    const float* x2 = (const float*)d_in[2];
    const float* x3 = (const float*)d_in[3];
    float* out = (float*)d_out;

    const int n = in_sizes[0];  // B
    const int grid = (n + 127) / 128;
    wigner_kernel<<<grid, 128>>>(x0, x1, x2, x3, out, n);
}

// round 7
// speedup vs baseline: 5.4907x; 1.1637x over previous
#include <cuda_runtime.h>

// ---------------------------------------------------------------------------
// Compile-time Clebsch-Gordan coefficients (Racah formula), matching numpy ref.
// ---------------------------------------------------------------------------

__host__ __device__ constexpr double cfact(int n) {
    double r = 1.0;
    for (int i = 2; i <= n; ++i) r *= (double)i;
    return r;
}

__host__ __device__ constexpr double csqrt_(double x) {
    if (x <= 0.0) return 0.0;
    double g = x > 1.0 ? x : 1.0;
    for (int i = 0; i < 100; ++i) g = 0.5 * (g + x / g);
    return g;
}

__host__ __device__ constexpr double cg_elem(int l1, int l2, int L, int m1, int m2) {
    const int M = m1 + m2;
    if (M < -L || M > L) return 0.0;
    const double pref0 = csqrt_((2.0 * L + 1.0) * cfact(L + l1 - l2) * cfact(L - l1 + l2) *
                                cfact(l1 + l2 - L) / cfact(l1 + l2 + L + 1));
    const double pref = pref0 * csqrt_(cfact(L + M) * cfact(L - M) * cfact(l1 - m1) *
                                       cfact(l1 + m1) * cfact(l2 - m2) * cfact(l2 + m2));
    double s = 0.0;
    for (int k = 0; k <= l1 + l2 - L; ++k) {
        if (l1 - m1 - k < 0 || l2 + m2 - k < 0 || L - l2 + m1 + k < 0 || L - l1 - m2 + k < 0)
            continue;
        const double d = cfact(k) * cfact(l1 + l2 - L - k) * cfact(l1 - m1 - k) *
                         cfact(l2 + m2 - k) * cfact(L - l2 + m1 + k) * cfact(L - l1 - m2 + k);
        s += ((k & 1) ? -1.0 : 1.0) / d;
    }
    return pref * s;
}

__host__ __device__ constexpr bool cg_nz(double c) { return c > 1e-12 || c < -1e-12; }

__host__ __device__ constexpr bool okL(int l1, int l2, int L, int a, int b) {
    const int off = l1 + l2 - L;
    const int mu = a + b - off;
    return mu >= 0 && mu <= 2 * L && cg_nz(cg_elem(l1, l2, L, a - l1, b - l2));
}

__host__ __device__ constexpr bool pair_any(int l1, int l2, int Lmin, int Lmax,
                                            int p, int q, int m, int n) {
    for (int L = Lmin; L <= Lmax; ++L)
        if (okL(l1, l2, L, m, n) && okL(l1, l2, L, p, q)) return true;
    return false;
}

__host__ __device__ constexpr bool col_any_p(int l1, int l2, int Lmin, int Lmax, int p, int q) {
    for (int L = Lmin; L <= Lmax; ++L)
        if (okL(l1, l2, L, p, q)) return true;
    return false;
}

__host__ __device__ constexpr bool col_any_q(int l1, int l2, int Lmin, int Lmax, int q, bool sym) {
    const int pmax = sym ? q : 2 * l1;
    for (int p = 0; p <= pmax; ++p)
        if (col_any_p(l1, l2, Lmin, Lmax, p, q)) return true;
    return false;
}

// any valid n >= nlo for row m of column (p,q)
__host__ __device__ constexpr bool row_any(int l1, int l2, int Lmin, int Lmax,
                                           int p, int q, int m, int nlo) {
    for (int nn = nlo; nn <= 2 * l2; ++nn)
        if (pair_any(l1, l2, Lmin, Lmax, p, q, m, nn)) return true;
    return false;
}

// ---------------------------------------------------------------------------
// Smem operand wrapper (linear layout: this thread's matrix at p[0..d*d)).
// ---------------------------------------------------------------------------

struct SmemMat {
    const float* p;
    template <int I> __device__ __forceinline__ float at() const { return p[I]; }
};

template <int d, int col, class M, int i = 0>
__device__ __forceinline__ void load_col(const M& mat, float (&dst)[d]) {
    if constexpr (i < d) {
        dst[i] = mat.template at<i * d + col>();
        load_col<d, col, M, i + 1>(mat, dst);
    }
}

// ---------------------------------------------------------------------------
// Accumulator group
// ---------------------------------------------------------------------------

struct EAcc {
    float e0[1];
    float e1[9];
    float e2[25];
    float e3[49];
};

template <int L> __device__ __forceinline__ auto& getE(EAcc& a) {
    if constexpr (L == 0) return a.e0;
    else if constexpr (L == 1) return a.e1;
    else if constexpr (L == 2) return a.e2;
    else return a.e3;
}

template <int N>
__device__ __forceinline__ void zeroa(float (&e)[N]) {
#pragma unroll
    for (int i = 0; i < N; ++i) e[i] = 0.f;
}

// ---------------------------------------------------------------------------
// Shared-product CG scatter: one FMUL per (m,n,p,q), one FFMA-imm per valid L.
// ---------------------------------------------------------------------------

template <int l1, int l2, int p, int q, int m, int n, int W, int L, int Lmax>
__device__ __forceinline__ void l_scatter(float prod, EAcc& acc) {
    if constexpr (L <= Lmax) {
        if constexpr (okL(l1, l2, L, m, n) && okL(l1, l2, L, p, q)) {
            constexpr int off = l1 + l2 - L, DL = 2 * L + 1;
            constexpr int mu = m + n - off, nu = p + q - off;
            constexpr float w = (float)((double)W * cg_elem(l1, l2, L, m - l1, n - l2) *
                                        cg_elem(l1, l2, L, p - l1, q - l2));
            getE<L>(acc)[mu * DL + nu] = __fmaf_rn(w, prod, getE<L>(acc)[mu * DL + nu]);
        }
        l_scatter<l1, l2, p, q, m, n, W, L + 1, Lmax>(prod, acc);
    }
}

// inner n loop: products of one A-scalar (am) against cached bcol
template <int l1, int l2, int p, int q, int m, int BW, bool SYMIN, int Lmin, int Lmax, int n>
__device__ __forceinline__ void n_loop(float am, const float (&bcol)[2 * l2 + 1], EAcc& acc) {
    if constexpr (n < 2 * l2 + 1) {
        if constexpr (!(SYMIN && m > n) && pair_any(l1, l2, Lmin, Lmax, p, q, m, n)) {
            float prod = am * bcol[n];
            l_scatter<l1, l2, p, q, m, n, BW*((SYMIN && m < n) ? 2 : 1), Lmin, Lmax>(prod, acc);
        }
        n_loop<l1, l2, p, q, m, BW, SYMIN, Lmin, Lmax, n + 1>(am, bcol, acc);
    }
}

// m loop: load A[m,p] on demand (1 scalar LDS), run n loop
template <int l1, int l2, int p, int q, int BW, int Lmin, int Lmax, class MA, int m = 0>
__device__ __forceinline__ void m_loop(const MA& A, const float (&bcol)[2 * l2 + 1], EAcc& acc) {
    constexpr int d1 = 2 * l1 + 1;
    if constexpr (m < d1) {
        if constexpr (row_any(l1, l2, Lmin, Lmax, p, q, m, 0)) {
            float am = A.template at<m * d1 + p>();
            n_loop<l1, l2, p, q, m, BW, false, Lmin, Lmax, 0>(am, bcol, acc);
        }
        m_loop<l1, l2, p, q, BW, Lmin, Lmax, MA, m + 1>(A, bcol, acc);
    }
}

// diagonal column of a symmetric self term (p == q): both operands from bcol
template <int l, int q, int Lmin, int Lmax, int m = 0>
__device__ __forceinline__ void m_loop_diag(const float (&bcol)[2 * l + 1], EAcc& acc) {
    if constexpr (m < 2 * l + 1) {
        if constexpr (row_any(l, l, Lmin, Lmax, q, q, m, m)) {
            n_loop<l, l, q, q, m, 1, true, Lmin, Lmax, m>(bcol[m], bcol, acc);
        }
        m_loop_diag<l, q, Lmin, Lmax, m + 1>(bcol, acc);
    }
}

// ----- cross term (A != B), weight BW -----

template <int l1, int l2, int BW, int Lmin, int Lmax, class MA, int q, int p = 0>
__device__ __forceinline__ void p_multi(const MA& A, const float (&bcol)[2 * l2 + 1], EAcc& acc) {
    constexpr int d1 = 2 * l1 + 1;
    if constexpr (p < d1) {
        if constexpr (col_any_p(l1, l2, Lmin, Lmax, p, q)) {
            m_loop<l1, l2, p, q, BW, Lmin, Lmax, MA>(A, bcol, acc);
        }
        p_multi<l1, l2, BW, Lmin, Lmax, MA, q, p + 1>(A, bcol, acc);
    }
}

template <int l1, int l2, int BW, int Lmin, int Lmax, class MA, class MB, int q = 0>
__device__ __forceinline__ void term_multi(const MA& A, const MB& Bm, EAcc& acc) {
    constexpr int d2 = 2 * l2 + 1;
    if constexpr (q < d2) {
        if constexpr (col_any_q(l1, l2, Lmin, Lmax, q, false)) {
            float bcol[d2];
            load_col<d2, q>(Bm, bcol);
            p_multi<l1, l2, BW, Lmin, Lmax, MA, q>(A, bcol, acc);
        }
        term_multi<l1, l2, BW, Lmin, Lmax, MA, MB, q + 1>(A, Bm, acc);
    }
}

// ----- symmetric self term A(x)A: p<q weight 2 full inner; p==q inner m<=n -----

template <int l, int Lmin, int Lmax, class MA, int q, int p = 0>
__device__ __forceinline__ void p_sym_multi(const MA& A, const float (&bcol)[2 * l + 1],
                                            EAcc& acc) {
    if constexpr (p <= q) {
        if constexpr (col_any_p(l, l, Lmin, Lmax, p, q)) {
            if constexpr (p < q) {
                m_loop<l, l, p, q, 2, Lmin, Lmax, MA>(A, bcol, acc);
            } else {
                m_loop_diag<l, q, Lmin, Lmax>(bcol, acc);
            }
        }
        p_sym_multi<l, Lmin, Lmax, MA, q, p + 1>(A, bcol, acc);
    }
}

template <int l, int Lmin, int Lmax, class MA, int q = 0>
__device__ __forceinline__ void term_sym_multi(const MA& A, EAcc& acc) {
    constexpr int d = 2 * l + 1;
    if constexpr (q < d) {
        if constexpr (col_any_q(l, l, Lmin, Lmax, q, true)) {
            float bcol[d];
            load_col<d, q>(A, bcol);
            p_sym_multi<l, Lmin, Lmax, MA, q>(A, bcol, acc);
        }
        term_sym_multi<l, Lmin, Lmax, MA, q + 1>(A, acc);
    }
}

// ----- (0,l) degenerate term: e_l[i] += t * X_l[i] -----

template <int N, class M, int i = 0>
__device__ __forceinline__ void axpy_sm(float t, const M& X, float (&e)[N]) {
    if constexpr (i < N) {
        e[i] = __fmaf_rn(t, X.template at<i>(), e[i]);
        axpy_sm<N, M, i + 1>(t, X, e);
    }
}

// ----- L=0 contractions -----

template <int L, class MB, int ij = 0>
__device__ __forceinline__ void invar_mat(const float (&A)[(2 * L + 1) * (2 * L + 1)],
                                          const MB& Bm, float& s) {
    constexpr int D = 2 * L + 1;
    if constexpr (ij < D * D) {
        constexpr int i = ij / D, j = ij % D;
        constexpr float w = (((i + j) & 1) ? -1.0f : 1.0f) / (float)D;
        s = __fmaf_rn(w, A[ij] * Bm.template at<(D - 1 - i) * D + (D - 1 - j)>(), s);
        invar_mat<L, MB, ij + 1>(A, Bm, s);
    }
}

template <int L, int ij = 0>
__device__ __forceinline__ void invar_self(const float (&A)[(2 * L + 1) * (2 * L + 1)],
                                           float& s) {
    constexpr int D = 2 * L + 1, DD = D * D;
    if constexpr (ij <= (DD - 1) / 2) {
        constexpr int i = ij / D, j = ij % D;
        constexpr float base = (ij == DD - 1 - ij) ? 1.0f : 2.0f;
        constexpr float w = (((i + j) & 1) ? -base : base) / (float)D;
        s = __fmaf_rn(w, A[ij] * A[DD - 1 - ij], s);
        invar_self<L, ij + 1>(A, s);
    }
}

// ---------------------------------------------------------------------------
// Kernel: one thread per batch element. Linear smem staging (no transpose,
// odd row-lengths 9/25/49 make per-thread reads bank-conflict-free).
// Two sigma-parity phases; 5 CTAs/SM (96-reg cap) for latency hiding.
// ---------------------------------------------------------------------------

// float offsets of each region in smem
constexpr int O1 = 0, O2 = 1152, O3 = 4352, SM_FLOATS = 10624;  // 83*128

__global__ void __launch_bounds__(128, 5)
wigner_kernel(const float* __restrict__ gx0, const float* __restrict__ gx1,
              const float* __restrict__ gx2, const float* __restrict__ gx3,
              float* __restrict__ out, int n) {
    __shared__ float sm[SM_FLOATS];
    const int tid = threadIdx.x;
    const int base = blockIdx.x * 128;

    if (base + 128 <= n) {  // full CTA: vectorized linear copy
        const float4* g1 = (const float4*)(gx1 + (size_t)base * 9);
        const float4* g2 = (const float4*)(gx2 + (size_t)base * 25);
        const float4* g3 = (const float4*)(gx3 + (size_t)base * 49);
        float4* s = (float4*)sm;
#pragma unroll
        for (int i = tid; i < 288; i += 128) s[i] = g1[i];
#pragma unroll
        for (int i = tid; i < 800; i += 128) s[288 + i] = g2[i];
#pragma unroll
        for (int i = tid; i < 1568; i += 128) s[1088 + i] = g3[i];
    } else {  // tail CTA: scalar with bounds
        const int l1c = (n - base) * 9, l2c = (n - base) * 25, l3c = (n - base) * 49;
        for (int i = tid; i < 1152; i += 128) sm[O1 + i] = (i < l1c) ? gx1[base * 9 + i] : 0.f;
        for (int i = tid; i < 3200; i += 128) sm[O2 + i] = (i < l2c) ? gx2[base * 25 + i] : 0.f;
        for (int i = tid; i < 6272; i += 128) sm[O3 + i] = (i < l3c) ? gx3[base * 49 + i] : 0.f;
    }
    __syncthreads();

    const int b = base + tid;
    const bool valid = (b < n);
    const float X0 = valid ? gx0[b] : 0.f;

    const SmemMat S1{sm + O1 + tid * 9};
    const SmemMat S2{sm + O2 + tid * 25};
    const SmemMat S3{sm + O3 + tid * 49};

    float out2 = 0.f, out3 = 0.f;

    {  // ---------------- Phase A: terms with l1+l2 even ----------------
        EAcc A_;
        zeroa(A_.e0); zeroa(A_.e1); zeroa(A_.e2); zeroa(A_.e3);

        A_.e0[0] = X0 * X0;                    // (0,0) -> L=0
        term_sym_multi<1, 0, 2>(S1, A_);       // (1,1) -> L=0,1,2
        term_sym_multi<2, 0, 3>(S2, A_);       // (2,2) -> L=0..3
        term_sym_multi<3, 0, 3>(S3, A_);       // (3,3) -> L=0..3
        axpy_sm<25>(X0 + X0, S2, A_.e2);       // (0,2)x2 -> L=2
        term_multi<1, 3, 2, 2, 3>(S1, S3, A_); // (1,3)x2 -> L=2,3

        out2 = __fmaf_rn(A_.e0[0], X0, out2);
        out3 = __fmaf_rn(A_.e0[0], A_.e0[0], out3);
        invar_self<1>(A_.e1, out3);            // (1,-)
        invar_mat<2>(A_.e2, S2, out2);         // (2,+) x X2
        invar_self<2>(A_.e2, out3);
        invar_self<3>(A_.e3, out3);            // (3,-)

        if (valid) {                           // retire out0/out1 now (frees regs)
            out[b * 4 + 0] = X0;
            out[b * 4 + 1] = A_.e0[0];
        }
    }
    __syncthreads();
    {  // ---------------- Phase B: terms with l1+l2 odd ----------------
        EAcc Bb;
        zeroa(Bb.e1); zeroa(Bb.e2); zeroa(Bb.e3);

        axpy_sm<9>(X0 + X0, S1, Bb.e1);        // (0,1)x2 -> L=1
        term_multi<1, 2, 2, 1, 3>(S1, S2, Bb); // (1,2)x2 -> L=1..3
        term_multi<2, 3, 2, 1, 3>(S2, S3, Bb); // (2,3)x2 -> L=1..3
        axpy_sm<49>(X0 + X0, S3, Bb.e3);       // (0,3)x2 -> L=3

        invar_mat<1>(Bb.e1, S1, out2);         // (1,+) x X1
        invar_self<1>(Bb.e1, out3);
        invar_self<2>(Bb.e2, out3);            // (2,-)
        invar_mat<3>(Bb.e3, S3, out2);         // (3,+) x X3
        invar_self<3>(Bb.e3, out3);
    }

    if (valid) {
        out[b * 4 + 2] = out2;
        out[b * 4 + 3] = out3;
    }
}

// ---------------------------------------------------------------------------
// Harness entry point
// ---------------------------------------------------------------------------

extern "C" void kernel_launch(void* const* d_in, const int* in_sizes, int n_in,
                              void* d_out, int out_size) {
    const float* x0 = (const float*)d_in[0];
    const float* x1 = (const float*)d_in[1];
    const float* x2 = (const float*)d_in[2];
    const float* x3 = (const float*)d_in[3];
    float* out = (float*)d_out;

    // Maximize smem carveout so 5 CTAs x 42.5KB fit per SM (hint; not a graph op).
    static bool attr_set = false;
    if (!attr_set) {
        cudaFuncSetAttribute(wigner_kernel,
                             cudaFuncAttributePreferredSharedMemoryCarveout, 100);
        attr_set = true;
    }

    const int n = in_sizes[0];  // B
    const int grid = (n + 127) / 128;
    wigner_kernel<<<grid, 128>>>(x0, x1, x2, x3, out, n);
}

// round 8
// speedup vs baseline: 5.8564x; 1.0666x over previous
#include <cuda_runtime.h>

// ---------------------------------------------------------------------------
// Compile-time Clebsch-Gordan coefficients (Racah formula), matching numpy ref.
// ---------------------------------------------------------------------------

__host__ __device__ constexpr double cfact(int n) {
    double r = 1.0;
    for (int i = 2; i <= n; ++i) r *= (double)i;
    return r;
}

__host__ __device__ constexpr double csqrt_(double x) {
    if (x <= 0.0) return 0.0;
    double g = x > 1.0 ? x : 1.0;
    for (int i = 0; i < 100; ++i) g = 0.5 * (g + x / g);
    return g;
}

__host__ __device__ constexpr double cg_elem(int l1, int l2, int L, int m1, int m2) {
    const int M = m1 + m2;
    if (M < -L || M > L) return 0.0;
    const double pref0 = csqrt_((2.0 * L + 1.0) * cfact(L + l1 - l2) * cfact(L - l1 + l2) *
                                cfact(l1 + l2 - L) / cfact(l1 + l2 + L + 1));
    const double pref = pref0 * csqrt_(cfact(L + M) * cfact(L - M) * cfact(l1 - m1) *
                                       cfact(l1 + m1) * cfact(l2 - m2) * cfact(l2 + m2));
    double s = 0.0;
    for (int k = 0; k <= l1 + l2 - L; ++k) {
        if (l1 - m1 - k < 0 || l2 + m2 - k < 0 || L - l2 + m1 + k < 0 || L - l1 - m2 + k < 0)
            continue;
        const double d = cfact(k) * cfact(l1 + l2 - L - k) * cfact(l1 - m1 - k) *
                         cfact(l2 + m2 - k) * cfact(L - l2 + m1 + k) * cfact(L - l1 - m2 + k);
        s += ((k & 1) ? -1.0 : 1.0) / d;
    }
    return pref * s;
}

__host__ __device__ constexpr bool cg_nz(double c) { return c > 1e-12 || c < -1e-12; }

__host__ __device__ constexpr bool okL(int l1, int l2, int L, int a, int b) {
    const int off = l1 + l2 - L;
    const int mu = a + b - off;
    return mu >= 0 && mu <= 2 * L && cg_nz(cg_elem(l1, l2, L, a - l1, b - l2));
}

__host__ __device__ constexpr bool pair_any(int l1, int l2, int Lmin, int Lmax,
                                            int p, int q, int m, int n) {
    for (int L = Lmin; L <= Lmax; ++L)
        if (okL(l1, l2, L, m, n) && okL(l1, l2, L, p, q)) return true;
    return false;
}

__host__ __device__ constexpr bool col_any_p(int l1, int l2, int Lmin, int Lmax, int p, int q) {
    for (int L = Lmin; L <= Lmax; ++L)
        if (okL(l1, l2, L, p, q)) return true;
    return false;
}

__host__ __device__ constexpr bool col_any_q(int l1, int l2, int Lmin, int Lmax, int q, bool sym) {
    const int pmax = sym ? q : 2 * l1;
    for (int p = 0; p <= pmax; ++p)
        if (col_any_p(l1, l2, Lmin, Lmax, p, q)) return true;
    return false;
}

__host__ __device__ constexpr bool row_any(int l1, int l2, int Lmin, int Lmax,
                                           int p, int q, int m, int nlo) {
    for (int nn = nlo; nn <= 2 * l2; ++nn)
        if (pair_any(l1, l2, Lmin, Lmax, p, q, m, nn)) return true;
    return false;
}

// ---------------------------------------------------------------------------
// Smem operand wrapper (linear layout: this thread's matrix at p[0..d*d)).
// ---------------------------------------------------------------------------

struct SmemMat {
    const float* p;
    template <int I> __device__ __forceinline__ float at() const { return p[I]; }
};

template <int d, int col, class M, int i = 0>
__device__ __forceinline__ void load_col(const M& mat, float (&dst)[d]) {
    if constexpr (i < d) {
        dst[i] = mat.template at<i * d + col>();
        load_col<d, col, M, i + 1>(mat, dst);
    }
}

// ---------------------------------------------------------------------------
// Accumulator group (each pass touches only a subset; SROA drops the rest)
// ---------------------------------------------------------------------------

struct EAcc {
    float e0[1];
    float e1[9];
    float e2[25];
    float e3[49];
};

template <int L> __device__ __forceinline__ auto& getE(EAcc& a) {
    if constexpr (L == 0) return a.e0;
    else if constexpr (L == 1) return a.e1;
    else if constexpr (L == 2) return a.e2;
    else return a.e3;
}

template <int N>
__device__ __forceinline__ void zeroa(float (&e)[N]) {
#pragma unroll
    for (int i = 0; i < N; ++i) e[i] = 0.f;
}

// ---------------------------------------------------------------------------
// Shared-product CG scatter: one FMUL per (m,n,p,q), one FFMA-imm per valid L.
// ---------------------------------------------------------------------------

template <int l1, int l2, int p, int q, int m, int n, int W, int L, int Lmax>
__device__ __forceinline__ void l_scatter(float prod, EAcc& acc) {
    if constexpr (L <= Lmax) {
        if constexpr (okL(l1, l2, L, m, n) && okL(l1, l2, L, p, q)) {
            constexpr int off = l1 + l2 - L, DL = 2 * L + 1;
            constexpr int mu = m + n - off, nu = p + q - off;
            constexpr float w = (float)((double)W * cg_elem(l1, l2, L, m - l1, n - l2) *
                                        cg_elem(l1, l2, L, p - l1, q - l2));
            getE<L>(acc)[mu * DL + nu] = __fmaf_rn(w, prod, getE<L>(acc)[mu * DL + nu]);
        }
        l_scatter<l1, l2, p, q, m, n, W, L + 1, Lmax>(prod, acc);
    }
}

template <int l1, int l2, int p, int q, int m, int BW, bool SYMIN, int Lmin, int Lmax, int n>
__device__ __forceinline__ void n_loop(float am, const float (&bcol)[2 * l2 + 1], EAcc& acc) {
    if constexpr (n < 2 * l2 + 1) {
        if constexpr (!(SYMIN && m > n) && pair_any(l1, l2, Lmin, Lmax, p, q, m, n)) {
            float prod = am * bcol[n];
            l_scatter<l1, l2, p, q, m, n, BW*((SYMIN && m < n) ? 2 : 1), Lmin, Lmax>(prod, acc);
        }
        n_loop<l1, l2, p, q, m, BW, SYMIN, Lmin, Lmax, n + 1>(am, bcol, acc);
    }
}

template <int l1, int l2, int p, int q, int BW, int Lmin, int Lmax, class MA, int m = 0>
__device__ __forceinline__ void m_loop(const MA& A, const float (&bcol)[2 * l2 + 1], EAcc& acc) {
    constexpr int d1 = 2 * l1 + 1;
    if constexpr (m < d1) {
        if constexpr (row_any(l1, l2, Lmin, Lmax, p, q, m, 0)) {
            float am = A.template at<m * d1 + p>();
            n_loop<l1, l2, p, q, m, BW, false, Lmin, Lmax, 0>(am, bcol, acc);
        }
        m_loop<l1, l2, p, q, BW, Lmin, Lmax, MA, m + 1>(A, bcol, acc);
    }
}

template <int l, int q, int Lmin, int Lmax, int m = 0>
__device__ __forceinline__ void m_loop_diag(const float (&bcol)[2 * l + 1], EAcc& acc) {
    if constexpr (m < 2 * l + 1) {
        if constexpr (row_any(l, l, Lmin, Lmax, q, q, m, m)) {
            n_loop<l, l, q, q, m, 1, true, Lmin, Lmax, m>(bcol[m], bcol, acc);
        }
        m_loop_diag<l, q, Lmin, Lmax, m + 1>(bcol, acc);
    }
}

// ----- cross term (A != B), weight BW -----

template <int l1, int l2, int BW, int Lmin, int Lmax, class MA, int q, int p = 0>
__device__ __forceinline__ void p_multi(const MA& A, const float (&bcol)[2 * l2 + 1], EAcc& acc) {
    constexpr int d1 = 2 * l1 + 1;
    if constexpr (p < d1) {
        if constexpr (col_any_p(l1, l2, Lmin, Lmax, p, q)) {
            m_loop<l1, l2, p, q, BW, Lmin, Lmax, MA>(A, bcol, acc);
        }
        p_multi<l1, l2, BW, Lmin, Lmax, MA, q, p + 1>(A, bcol, acc);
    }
}

template <int l1, int l2, int BW, int Lmin, int Lmax, class MA, class MB, int q = 0>
__device__ __forceinline__ void term_multi(const MA& A, const MB& Bm, EAcc& acc) {
    constexpr int d2 = 2 * l2 + 1;
    if constexpr (q < d2) {
        if constexpr (col_any_q(l1, l2, Lmin, Lmax, q, false)) {
            float bcol[d2];
            load_col<d2, q>(Bm, bcol);
            p_multi<l1, l2, BW, Lmin, Lmax, MA, q>(A, bcol, acc);
        }
        term_multi<l1, l2, BW, Lmin, Lmax, MA, MB, q + 1>(A, Bm, acc);
    }
}

// ----- symmetric self term A(x)A: p<q weight 2 full inner; p==q inner m<=n -----

template <int l, int Lmin, int Lmax, class MA, int q, int p = 0>
__device__ __forceinline__ void p_sym_multi(const MA& A, const float (&bcol)[2 * l + 1],
                                            EAcc& acc) {
    if constexpr (p <= q) {
        if constexpr (col_any_p(l, l, Lmin, Lmax, p, q)) {
            if constexpr (p < q) {
                m_loop<l, l, p, q, 2, Lmin, Lmax, MA>(A, bcol, acc);
            } else {
                m_loop_diag<l, q, Lmin, Lmax>(bcol, acc);
            }
        }
        p_sym_multi<l, Lmin, Lmax, MA, q, p + 1>(A, bcol, acc);
    }
}

template <int l, int Lmin, int Lmax, class MA, int q = 0>
__device__ __forceinline__ void term_sym_multi(const MA& A, EAcc& acc) {
    constexpr int d = 2 * l + 1;
    if constexpr (q < d) {
        if constexpr (col_any_q(l, l, Lmin, Lmax, q, true)) {
            float bcol[d];
            load_col<d, q>(A, bcol);
            p_sym_multi<l, Lmin, Lmax, MA, q>(A, bcol, acc);
        }
        term_sym_multi<l, Lmin, Lmax, MA, q + 1>(A, acc);
    }
}

// ----- (0,l) degenerate term: e_l[i] += t * X_l[i] -----

template <int N, class M, int i = 0>
__device__ __forceinline__ void axpy_sm(float t, const M& X, float (&e)[N]) {
    if constexpr (i < N) {
        e[i] = __fmaf_rn(t, X.template at<i>(), e[i]);
        axpy_sm<N, M, i + 1>(t, X, e);
    }
}

// ----- L=0 contractions -----

template <int L, class MB, int ij = 0>
__device__ __forceinline__ void invar_mat(const float (&A)[(2 * L + 1) * (2 * L + 1)],
                                          const MB& Bm, float& s) {
    constexpr int D = 2 * L + 1;
    if constexpr (ij < D * D) {
        constexpr int i = ij / D, j = ij % D;
        constexpr float w = (((i + j) & 1) ? -1.0f : 1.0f) / (float)D;
        s = __fmaf_rn(w, A[ij] * Bm.template at<(D - 1 - i) * D + (D - 1 - j)>(), s);
        invar_mat<L, MB, ij + 1>(A, Bm, s);
    }
}

template <int L, int ij = 0>
__device__ __forceinline__ void invar_self(const float (&A)[(2 * L + 1) * (2 * L + 1)],
                                           float& s) {
    constexpr int D = 2 * L + 1, DD = D * D;
    if constexpr (ij <= (DD - 1) / 2) {
        constexpr int i = ij / D, j = ij % D;
        constexpr float base = (ij == DD - 1 - ij) ? 1.0f : 2.0f;
        constexpr float w = (((i + j) & 1) ? -base : base) / (float)D;
        s = __fmaf_rn(w, A[ij] * A[DD - 1 - ij], s);
        invar_self<L, ij + 1>(A, s);
    }
}

// ---------------------------------------------------------------------------
// Kernel: one thread per batch element, FOUR passes so peak live regs <= ~90:
//  A1: even terms, L{0,1} -> {e0,e1}   (small)
//  A2: even terms, L{2,3} -> {e2,e3}   (74 regs of acc)
//  B1: odd  terms, L{1}   -> {e1}      (small)
//  B2: odd  terms, L{2,3} -> {e2,e3}   (74 regs of acc)
// Products valid in both L-halves are recomputed (small set: low-L validity
// bands are narrow). 5 CTAs/SM at 96 regs, spill-free.
// ---------------------------------------------------------------------------

// float offsets of smem regions
constexpr int O0 = 0, O1 = 128, O2 = 1280, O3 = 4480, SM_FLOATS = 10752;  // 84*128

__global__ void __launch_bounds__(128, 5)
wigner_kernel(const float* __restrict__ gx0, const float* __restrict__ gx1,
              const float* __restrict__ gx2, const float* __restrict__ gx3,
              float* __restrict__ out, int n) {
    __shared__ float sm[SM_FLOATS];
    const int tid = threadIdx.x;
    const int base = blockIdx.x * 128;

    if (base + 128 <= n) {  // full CTA: vectorized linear copy
        const float4* g0 = (const float4*)(gx0 + (size_t)base);
        const float4* g1 = (const float4*)(gx1 + (size_t)base * 9);
        const float4* g2 = (const float4*)(gx2 + (size_t)base * 25);
        const float4* g3 = (const float4*)(gx3 + (size_t)base * 49);
        float4* s = (float4*)sm;
        if (tid < 32) s[tid] = g0[tid];
#pragma unroll
        for (int i = tid; i < 288; i += 128) s[32 + i] = g1[i];
#pragma unroll
        for (int i = tid; i < 800; i += 128) s[320 + i] = g2[i];
#pragma unroll
        for (int i = tid; i < 1568; i += 128) s[1120 + i] = g3[i];
    } else {  // tail CTA: scalar with bounds
        const int c = n - base;
        for (int i = tid; i < 128; i += 128) sm[O0 + i] = (i < c) ? gx0[base + i] : 0.f;
        for (int i = tid; i < 1152; i += 128) sm[O1 + i] = (i < c * 9) ? gx1[base * 9 + i] : 0.f;
        for (int i = tid; i < 3200; i += 128) sm[O2 + i] = (i < c * 25) ? gx2[base * 25 + i] : 0.f;
        for (int i = tid; i < 6272; i += 128) sm[O3 + i] = (i < c * 49) ? gx3[base * 49 + i] : 0.f;
    }
    __syncthreads();

    const int b = base + tid;
    const bool valid = (b < n);

    const SmemMat S1{sm + O1 + tid * 9};
    const SmemMat S2{sm + O2 + tid * 25};
    const SmemMat S3{sm + O3 + tid * 49};

    float out2, out3;

    {  // ----- Pass A1: even terms, L in {0,1} -> e0, e1 -----
        EAcc a;
        zeroa(a.e0); zeroa(a.e1);
        const float X0 = sm[O0 + tid];
        a.e0[0] = X0 * X0;                     // (0,0) -> L=0
        term_sym_multi<1, 0, 1>(S1, a);        // (1,1) -> L=0,1
        term_sym_multi<2, 0, 1>(S2, a);        // (2,2) -> L=0,1
        term_sym_multi<3, 0, 1>(S3, a);        // (3,3) -> L=0,1
        out2 = a.e0[0] * X0;
        out3 = a.e0[0] * a.e0[0];
        invar_self<1>(a.e1, out3);             // (1,-)
        if (valid) {
            out[b * 4 + 0] = X0;
            out[b * 4 + 1] = a.e0[0];
        }
    }
    __syncthreads();
    {  // ----- Pass A2: even terms, L in {2,3} -> e2, e3 -----
        EAcc a;
        zeroa(a.e2); zeroa(a.e3);
        term_sym_multi<1, 2, 2>(S1, a);        // (1,1) -> L=2
        term_sym_multi<2, 2, 3>(S2, a);        // (2,2) -> L=2,3
        term_sym_multi<3, 2, 3>(S3, a);        // (3,3) -> L=2,3
        term_multi<1, 3, 2, 2, 3>(S1, S3, a);  // (1,3)x2 -> L=2,3
        const float X0 = sm[O0 + tid];
        axpy_sm<25>(X0 + X0, S2, a.e2);        // (0,2)x2 -> L=2
        invar_mat<2>(a.e2, S2, out2);          // (2,+) x X2
        invar_self<2>(a.e2, out3);
        invar_self<3>(a.e3, out3);             // (3,-)
    }
    __syncthreads();
    {  // ----- Pass B1: odd terms, L = 1 -> e1 -----
        EAcc a;
        zeroa(a.e1);
        const float X0 = sm[O0 + tid];
        axpy_sm<9>(X0 + X0, S1, a.e1);         // (0,1)x2 -> L=1
        term_multi<1, 2, 2, 1, 1>(S1, S2, a);  // (1,2)x2 -> L=1
        term_multi<2, 3, 2, 1, 1>(S2, S3, a);  // (2,3)x2 -> L=1
        invar_mat<1>(a.e1, S1, out2);          // (1,+) x X1
        invar_self<1>(a.e1, out3);
    }
    __syncthreads();
    {  // ----- Pass B2: odd terms, L in {2,3} -> e2, e3 -----
        EAcc a;
        zeroa(a.e2); zeroa(a.e3);
        term_multi<1, 2, 2, 2, 3>(S1, S2, a);  // (1,2)x2 -> L=2,3
        term_multi<2, 3, 2, 2, 3>(S2, S3, a);  // (2,3)x2 -> L=2,3
        const float X0 = sm[O0 + tid];
        axpy_sm<49>(X0 + X0, S3, a.e3);        // (0,3)x2 -> L=3
        invar_self<2>(a.e2, out3);             // (2,-)
        invar_mat<3>(a.e3, S3, out2);          // (3,+) x X3
        invar_self<3>(a.e3, out3);
    }

    if (valid) {
        out[b * 4 + 2] = out2;
        out[b * 4 + 3] = out3;
    }
}

// ---------------------------------------------------------------------------
// Harness entry point
// ---------------------------------------------------------------------------

extern "C" void kernel_launch(void* const* d_in, const int* in_sizes, int n_in,
                              void* d_out, int out_size) {
    const float* x0 = (const float*)d_in[0];
    const float* x1 = (const float*)d_in[1];
    const float* x2 = (const float*)d_in[2];
    const float* x3 = (const float*)d_in[3];
    float* out = (float*)d_out;

    static bool attr_set = false;
    if (!attr_set) {
        cudaFuncSetAttribute(wigner_kernel,
                             cudaFuncAttributePreferredSharedMemoryCarveout, 100);
        attr_set = true;
    }

    const int n = in_sizes[0];  // B
    const int grid = (n + 127) / 128;
    wigner_kernel<<<grid, 128>>>(x0, x1, x2, x3, out, n);
}